// round 3
// baseline (speedup 1.0000x reference)
#include <cuda_runtime.h>
#include <math.h>
#include <stdint.h>

// Problem dims (fixed by the dataset)
#define NB 64
#define NO 1024
#define NI 1024
#define OT 4                      // o-rows per block (mu/sigma staged in smem)
#define BT 32                     // b-rows per block
#define MAIN_BLOCKS ((NO/OT) * (NB/BT))   // 256 * 2 = 512

// Scratch (no allocations allowed -> __device__ globals)
// partials per block: st (sum w^2 incl bias), sr (sum softplus(df)),
//                     se (sum eps_w^2), pb (bias posterior extras),
//                     ls (sum log sigma_w, counted twice)
__device__ double g_part[MAIN_BLOCKS][5];
__device__ int    g_counter;   // zero-initialized; reset by last block each run

// ---------------------------------------------------------------------------
// Main kernel: fused softplus(rho) + GEMV + prior/posterior stats + finalize
// block: 256 threads = 8 warps. Tile = OT o-rows x BT b-rows.
// ---------------------------------------------------------------------------
__global__ __launch_bounds__(256, 4) void main_kernel(
    const float* __restrict__ x,
    const float* __restrict__ wmu,
    const float* __restrict__ wrho,
    const float* __restrict__ bmu,
    const float* __restrict__ brho,
    const float* __restrict__ epsw,
    const float* __restrict__ epsb,
    float* __restrict__ out)
{
    __shared__ float  mu_s[OT * NI];   // 16KB
    __shared__ float  sg_s[OT * NI];   // 16KB
    __shared__ float  red[256];        // 1KB  (float block reduce)
    __shared__ double dred[256];       // 2KB  (finalize double reduce)
    __shared__ int    is_last;

    const float KP   = 6.2146080984221914f;   // -log(0.002)
    const float C2   = 124999.5f;             // 1/(2*0.002^2) - 0.5
    const float NC2L = -180336.15876359287f;  // -C2 * log2(e)
    const float KPL2 = 8.96578433024671f;     // KP * log2(e)

    int t      = threadIdx.x;
    int ot     = blockIdx.x & ((NO / OT) - 1);   // 0..255
    int bh     = blockIdx.x >> 8;                // 0..1
    int o_base = ot * OT;
    int b_base = bh * BT;

    // stage mu and sigma=softplus(rho) for OT o-rows into smem (coalesced f4),
    // accumulating sum(log sigma) on the fly
    float lsig = 0.f;
#pragma unroll
    for (int k = 0; k < 4; k++) {
        int f   = t + k * 256;          // float4 index within tile (0..1023)
        int row = f >> 8;               // 256 float4 per 1024-wide row
        int col = (f & 255) << 2;
        float4 m = *reinterpret_cast<const float4*>(wmu + (size_t)(o_base + row) * NI + col);
        float4 r = *reinterpret_cast<const float4*>(wrho + (size_t)(o_base + row) * NI + col);
        float4 s;
        s.x = log1pf(__expf(r.x));
        s.y = log1pf(__expf(r.y));
        s.z = log1pf(__expf(r.z));
        s.w = log1pf(__expf(r.w));
        lsig += __logf(s.x) + __logf(s.y) + __logf(s.z) + __logf(s.w);
        *reinterpret_cast<float4*>(&mu_s[row * NI + col]) = m;
        *reinterpret_cast<float4*>(&sg_s[row * NI + col]) = s;
    }
    __syncthreads();

    int warp = t >> 5, lane = t & 31;
    float st = 0.f;   // sum of w^2 (prior, incl bias)
    float sr = 0.f;   // sum of softplus(df) (prior mixture correction)
    float se = 0.f;   // sum of eps_w^2 (posterior)
    float pb = 0.f;   // bias posterior extras

    // Branchless: per element contribute softplus(df) via product trick.
    // factor = 1 + exp2(df*log2e); df = KP - C2*w^2 (df <= 6.2146 => factor <= 501)
    // group of <=8 factors: product <= 501^8 ~ 4e21 < FLT_MAX. One __logf per 8.
#define BODY(EC, MC, SC, XC, DI, PACC)                            \
    {                                                             \
        float w_ = fmaf((SC), (EC), (MC));                        \
        d[DI]    = fmaf(w_, (XC), d[DI]);                         \
        se       = fmaf((EC), (EC), se);                          \
        float t_ = w_ * w_;                                       \
        st += t_;                                                 \
        float u_ = fmaf(t_, NC2L, KPL2);                          \
        float e_ = exp2f(u_);                                     \
        PACC = fmaf(PACC, e_, PACC);                              \
    }

    for (int bb = 0; bb < 4; bb++) {
        int b = b_base + warp + bb * 8;
        float d[OT];
#pragma unroll
        for (int oi = 0; oi < OT; oi++) d[oi] = 0.f;

        const float4* xrow4 = reinterpret_cast<const float4*>(x + (size_t)b * NI);
        const float*  erow  = epsw + (((size_t)(b * NO + o_base)) << 10);
        const float4* ep[OT];
#pragma unroll
        for (int oi = 0; oi < OT; oi++)
            ep[oi] = reinterpret_cast<const float4*>(erow + (size_t)oi * NI);

        // software pipeline: prefetch next j's eps while computing current
        float4 ev[OT], en[OT];
#pragma unroll
        for (int oi = 0; oi < OT; oi++)
            ev[oi] = __ldcs(ep[oi] + lane);          // j = 0

#pragma unroll
        for (int j = 0; j < 8; j++) {
            if (j < 7) {
#pragma unroll
                for (int oi = 0; oi < OT; oi++)
                    en[oi] = __ldcs(ep[oi] + lane + (j + 1) * 32);
            }
            int bi4 = j * 32 + lane;                 // float4 index in row
            int bi  = bi4 << 2;                      // float index
            float4 xv = xrow4[bi4];

            float p0 = 1.f, p1 = 1.f;                // two 4-deep chains per 8-group
#pragma unroll
            for (int oi = 0; oi < OT; oi++) {
                float4 m = *reinterpret_cast<const float4*>(&mu_s[oi * NI + bi]);
                float4 s = *reinterpret_cast<const float4*>(&sg_s[oi * NI + bi]);
                BODY(ev[oi].x, m.x, s.x, xv.x, oi, p0)
                BODY(ev[oi].y, m.y, s.y, xv.y, oi, p1)
                BODY(ev[oi].z, m.z, s.z, xv.z, oi, p0)
                BODY(ev[oi].w, m.w, s.w, xv.w, oi, p1)
                if (oi == 1) {                       // close first 8-element group
                    sr += __logf(p0 * p1);
                    p0 = 1.f; p1 = 1.f;
                }
            }
            sr += __logf(p0 * p1);                   // close second 8-element group

#pragma unroll
            for (int oi = 0; oi < OT; oi++) ev[oi] = en[oi];
        }

        // reduce dots, add sampled bias, emit out[b,o]; lane0 folds bias stats
#pragma unroll
        for (int oi = 0; oi < OT; oi++) {
            float v = d[oi];
#pragma unroll
            for (int off = 16; off; off >>= 1)
                v += __shfl_down_sync(0xffffffffu, v, off);
            if (lane == 0) {
                int o    = o_base + oi;
                float bs = log1pf(expf(brho[o]));          // softplus(bias_rho)
                float eb = epsb[b * NO + o];
                float bv = fmaf(bs, eb, bmu[o]);           // sampled bias
                out[b * NO + o] = v + bv;
                pb += -logf(bs) - 0.5f * eb * eb;          // bias posterior
                float tb = bv * bv;                        // bias prior
                st += tb;
                float dfb = fmaf(tb, -C2, KP);
                sr += fmaxf(dfb, 0.f);
                float fdb = fabsf(dfb);
                if (fdb < 15.f) sr += log1pf(expf(-fdb));
            }
        }
    }
#undef BODY

    // block reduction of the 5 accumulators -> deterministic double partials
    float acc[5] = {st, sr, se, pb, lsig};
#pragma unroll
    for (int q = 0; q < 5; q++) {
        __syncthreads();
        red[t] = acc[q];
        __syncthreads();
        for (int s = 128; s > 0; s >>= 1) {
            if (t < s) red[t] += red[t + s];
            __syncthreads();
        }
        if (t == 0) g_part[blockIdx.x][q] = (double)red[0];
    }

    // ---- last-block finalize (deterministic fixed-order double reduction) ----
    __threadfence();
    if (t == 0) {
        int old = atomicAdd(&g_counter, 1);
        is_last = (old == MAIN_BLOCKS - 1) ? 1 : 0;
    }
    __syncthreads();
    if (!is_last) return;
    __threadfence();

    double a[5] = {0, 0, 0, 0, 0};
    for (int i = t; i < MAIN_BLOCKS; i += 256)
#pragma unroll
        for (int q = 0; q < 5; q++) a[q] += g_part[i][q];

    double tot[5];
#pragma unroll
    for (int q = 0; q < 5; q++) {
        __syncthreads();
        dred[t] = a[q];
        __syncthreads();
        for (int s = 128; s > 0; s >>= 1) {
            if (t < s) dred[t] += dred[t + s];
            __syncthreads();
        }
        tot[q] = dred[0];
    }
    if (t == 0) {
        const double c   = 0.9189385332046727;     // log(sqrt(2*pi))
        const double l05 = -0.6931471805599453;    // log(0.5)
        const double Nw  = 67108864.0;             // B*O*I
        const double Nb2 = 65536.0;                // B*O
        // prior: per-element constant + (-0.5*sum w^2 + sum softplus(df))
        double lp    = (Nw + Nb2) * (l05 - c) - 0.5 * tot[0] + tot[1];
        // posterior: -N*c - B*sum(log sigma_w) - 0.5*sum(eps_w^2) + bias terms
        // lsig counted twice (bh=0 and bh=1 both stage it) -> 64/2 = 32
        double lpost = -(Nw + Nb2) * c - 32.0 * tot[4] - 0.5 * tot[2] + tot[3];
        out[NB * NO]     = (float)lp;
        out[NB * NO + 1] = (float)lpost;
        g_counter = 0;                              // reset for next graph replay
    }
}

// ---------------------------------------------------------------------------
extern "C" void kernel_launch(void* const* d_in, const int* in_sizes, int n_in,
                              void* d_out, int out_size)
{
    const float* x    = (const float*)d_in[0];   // (64,1024)
    const float* wmu  = (const float*)d_in[1];   // (1024,1024)
    const float* wrho = (const float*)d_in[2];   // (1024,1024)
    const float* bmu  = (const float*)d_in[3];   // (1024,)
    const float* brho = (const float*)d_in[4];   // (1024,)
    const float* epsw = (const float*)d_in[5];   // (64,1024,1024)
    const float* epsb = (const float*)d_in[6];   // (64,1024)
    float* out = (float*)d_out;                  // 65536 + 2

    main_kernel<<<MAIN_BLOCKS, 256>>>(x, wmu, wrho, bmu, brho, epsw, epsb, out);
}

// round 4
// speedup vs baseline: 1.2219x; 1.2219x over previous
#include <cuda_runtime.h>
#include <math.h>
#include <stdint.h>

// Problem dims (fixed by the dataset)
#define NB 64
#define NO 1024
#define NI 1024
#define OT 4                      // o-rows per block (mu/sigma staged in smem)
#define BT 32                     // b-rows per block
#define MAIN_BLOCKS ((NO/OT) * (NB/BT))   // 256 * 2 = 512

// Scratch (no allocations allowed -> __device__ globals)
// partials per block: st (sum w^2 incl bias), sr (sum softplus(df)),
//                     se (sum eps_w^2), pb (bias posterior extras),
//                     ls (sum log sigma_w, counted twice)
__device__ double g_part[MAIN_BLOCKS][5];
__device__ int    g_counter;   // zero-initialized; reset by last block each run

// ---------------------------------------------------------------------------
// Main kernel: fused softplus(rho) + GEMV + prior/posterior stats + finalize
// block: 256 threads = 8 warps. Tile = OT o-rows x BT b-rows.
// ---------------------------------------------------------------------------
__global__ __launch_bounds__(256, 4) void main_kernel(
    const float* __restrict__ x,
    const float* __restrict__ wmu,
    const float* __restrict__ wrho,
    const float* __restrict__ bmu,
    const float* __restrict__ brho,
    const float* __restrict__ epsw,
    const float* __restrict__ epsb,
    float* __restrict__ out)
{
    __shared__ float  mu_s[OT * NI];   // 16KB
    __shared__ float  sg_s[OT * NI];   // 16KB
    __shared__ float  red[256];        // 1KB  (float block reduce)
    __shared__ double dred[256];       // 2KB  (finalize double reduce)
    __shared__ int    is_last;

    const float KP   = 6.2146080984221914f;   // -log(0.002)
    const float C2   = 124999.5f;             // 1/(2*0.002^2) - 0.5
    const float NC2L = -180336.15876359287f;  // -C2 * log2(e)
    const float KPL2 = 8.96578433024671f;     // KP * log2(e)

    int t      = threadIdx.x;
    int ot     = blockIdx.x & ((NO / OT) - 1);   // 0..255
    int bh     = blockIdx.x >> 8;                // 0..1
    int o_base = ot * OT;
    int b_base = bh * BT;

    // stage mu and sigma=softplus(rho) for OT o-rows into smem (coalesced f4),
    // accumulating sum(log sigma) on the fly
    float lsig = 0.f;
#pragma unroll
    for (int k = 0; k < 4; k++) {
        int f   = t + k * 256;          // float4 index within tile (0..1023)
        int row = f >> 8;               // 256 float4 per 1024-wide row
        int col = (f & 255) << 2;
        float4 m = *reinterpret_cast<const float4*>(wmu + (size_t)(o_base + row) * NI + col);
        float4 r = *reinterpret_cast<const float4*>(wrho + (size_t)(o_base + row) * NI + col);
        float4 s;
        s.x = log1pf(__expf(r.x));
        s.y = log1pf(__expf(r.y));
        s.z = log1pf(__expf(r.z));
        s.w = log1pf(__expf(r.w));
        lsig += __logf(s.x) + __logf(s.y) + __logf(s.z) + __logf(s.w);
        *reinterpret_cast<float4*>(&mu_s[row * NI + col]) = m;
        *reinterpret_cast<float4*>(&sg_s[row * NI + col]) = s;
    }
    __syncthreads();

    int warp = t >> 5, lane = t & 31;
    float st = 0.f;   // sum of w^2 (prior, incl bias)
    float sr = 0.f;   // sum of softplus(df) (prior mixture correction)
    float se = 0.f;   // sum of eps_w^2 (posterior)
    float pb = 0.f;   // bias posterior extras

    // Branchless: per element contribute softplus(df) via product trick.
    // factor = 1 + exp2(df*log2e); df = KP - C2*w^2 (df <= 6.2146 => factor <= 501)
    // group of <=8 factors: product <= 501^8 ~ 4e21 < FLT_MAX. One __logf per 8.
#define BODY(EC, MC, SC, XC, DI, PACC)                            \
    {                                                             \
        float w_ = fmaf((SC), (EC), (MC));                        \
        d[DI]    = fmaf(w_, (XC), d[DI]);                         \
        se       = fmaf((EC), (EC), se);                          \
        float t_ = w_ * w_;                                       \
        st += t_;                                                 \
        float u_ = fmaf(t_, NC2L, KPL2);                          \
        float e_ = exp2f(u_);                                     \
        PACC = fmaf(PACC, e_, PACC);                              \
    }

    for (int bb = 0; bb < 4; bb++) {
        int b = b_base + warp + bb * 8;
        float d[OT];
#pragma unroll
        for (int oi = 0; oi < OT; oi++) d[oi] = 0.f;

        const float* xrow = x + (size_t)b * NI;
        const float* erow = epsw + (((size_t)(b * NO + o_base)) << 10);

        for (int j = 0; j < 8; j++) {
            int bi = (j << 7) + (lane << 2);
            float4 xv = *reinterpret_cast<const float4*>(xrow + bi);
            float4 ev[OT];
#pragma unroll
            for (int oi = 0; oi < OT; oi++)
                ev[oi] = *reinterpret_cast<const float4*>(erow + (size_t)oi * NI + bi);

            float p0 = 1.f, p1 = 1.f;   // two 4-deep chains per 8-group
#pragma unroll
            for (int oi = 0; oi < OT; oi++) {
                float4 m = *reinterpret_cast<const float4*>(&mu_s[oi * NI + bi]);
                float4 s = *reinterpret_cast<const float4*>(&sg_s[oi * NI + bi]);
                BODY(ev[oi].x, m.x, s.x, xv.x, oi, p0)
                BODY(ev[oi].y, m.y, s.y, xv.y, oi, p1)
                BODY(ev[oi].z, m.z, s.z, xv.z, oi, p0)
                BODY(ev[oi].w, m.w, s.w, xv.w, oi, p1)
                if (oi == 1) {          // close first 8-element group
                    sr += __logf(p0 * p1);
                    p0 = 1.f; p1 = 1.f;
                }
            }
            sr += __logf(p0 * p1);      // close second 8-element group
        }

        // reduce dots, add sampled bias, emit out[b,o]; lane0 folds bias stats
#pragma unroll
        for (int oi = 0; oi < OT; oi++) {
            float v = d[oi];
#pragma unroll
            for (int off = 16; off; off >>= 1)
                v += __shfl_down_sync(0xffffffffu, v, off);
            if (lane == 0) {
                int o    = o_base + oi;
                float bs = log1pf(expf(brho[o]));          // softplus(bias_rho)
                float eb = epsb[b * NO + o];
                float bv = fmaf(bs, eb, bmu[o]);           // sampled bias
                out[b * NO + o] = v + bv;
                pb += -logf(bs) - 0.5f * eb * eb;          // bias posterior
                float tb = bv * bv;                        // bias prior
                st += tb;
                float dfb = fmaf(tb, -C2, KP);
                sr += fmaxf(dfb, 0.f);
                float fdb = fabsf(dfb);
                if (fdb < 15.f) sr += log1pf(expf(-fdb));
            }
        }
    }
#undef BODY

    // block reduction of the 5 accumulators -> deterministic double partials
    float acc[5] = {st, sr, se, pb, lsig};
#pragma unroll
    for (int q = 0; q < 5; q++) {
        __syncthreads();
        red[t] = acc[q];
        __syncthreads();
        for (int s = 128; s > 0; s >>= 1) {
            if (t < s) red[t] += red[t + s];
            __syncthreads();
        }
        if (t == 0) g_part[blockIdx.x][q] = (double)red[0];
    }

    // ---- last-block finalize (deterministic fixed-order double reduction) ----
    __threadfence();
    if (t == 0) {
        int old = atomicAdd(&g_counter, 1);
        is_last = (old == MAIN_BLOCKS - 1) ? 1 : 0;
    }
    __syncthreads();
    if (!is_last) return;
    __threadfence();

    double a[5] = {0, 0, 0, 0, 0};
    for (int i = t; i < MAIN_BLOCKS; i += 256)
#pragma unroll
        for (int q = 0; q < 5; q++) a[q] += g_part[i][q];

    double tot[5];
#pragma unroll
    for (int q = 0; q < 5; q++) {
        __syncthreads();
        dred[t] = a[q];
        __syncthreads();
        for (int s = 128; s > 0; s >>= 1) {
            if (t < s) dred[t] += dred[t + s];
            __syncthreads();
        }
        tot[q] = dred[0];
    }
    if (t == 0) {
        const double c   = 0.9189385332046727;     // log(sqrt(2*pi))
        const double l05 = -0.6931471805599453;    // log(0.5)
        const double Nw  = 67108864.0;             // B*O*I
        const double Nb2 = 65536.0;                // B*O
        // prior: per-element constant + (-0.5*sum w^2 + sum softplus(df))
        double lp    = (Nw + Nb2) * (l05 - c) - 0.5 * tot[0] + tot[1];
        // posterior: -N*c - B*sum(log sigma_w) - 0.5*sum(eps_w^2) + bias terms
        // lsig counted twice (bh=0 and bh=1 both stage it) -> 64/2 = 32
        double lpost = -(Nw + Nb2) * c - 32.0 * tot[4] - 0.5 * tot[2] + tot[3];
        out[NB * NO]     = (float)lp;
        out[NB * NO + 1] = (float)lpost;
        g_counter = 0;                              // reset for next graph replay
    }
}

// ---------------------------------------------------------------------------
extern "C" void kernel_launch(void* const* d_in, const int* in_sizes, int n_in,
                              void* d_out, int out_size)
{
    const float* x    = (const float*)d_in[0];   // (64,1024)
    const float* wmu  = (const float*)d_in[1];   // (1024,1024)
    const float* wrho = (const float*)d_in[2];   // (1024,1024)
    const float* bmu  = (const float*)d_in[3];   // (1024,)
    const float* brho = (const float*)d_in[4];   // (1024,)
    const float* epsw = (const float*)d_in[5];   // (64,1024,1024)
    const float* epsb = (const float*)d_in[6];   // (64,1024)
    float* out = (float*)d_out;                  // 65536 + 2

    main_kernel<<<MAIN_BLOCKS, 256>>>(x, wmu, wrho, bmu, brho, epsw, epsb, out);
}